// round 1
// baseline (speedup 1.0000x reference)
#include <cuda_runtime.h>
#include <cstdint>

#define B_   8
#define T_   316
#define CIN_ 64
#define HF_  128
#define G_   32
#define E_   384

// out layout (flattened tuple, fp32):
// patches: B*T*CIN*8*8 = 10,354,688
// cx:      B*T         = 2,528
// cy:      B*T         = 2,528
// scale:   B*T         = 2,528
// fmap:    B*E*G*G     = 3,145,728
#define N_PATCHES (B_*T_*CIN_*64)
#define N_BT      (B_*T_)
#define N_FMAP    (B_*E_*G_*G_)

// scratch: owner map (which token owns each grid cell), per batch
__device__ int g_owner[B_ * G_ * G_];

// ---------------------------------------------------------------------------
// Kernel 0: init owner map to -1
// ---------------------------------------------------------------------------
__global__ void init_owner_kernel() {
    int idx = blockIdx.x * blockDim.x + threadIdx.x;
    if (idx < B_ * G_ * G_) g_owner[idx] = -1;
}

// ---------------------------------------------------------------------------
// Kernel 1: per-token meta -> cx, cy, scale_idx, owner scatter
// ---------------------------------------------------------------------------
__global__ void meta_kernel(const int* __restrict__ metas,
                            float* __restrict__ cx,
                            float* __restrict__ cy,
                            float* __restrict__ sc) {
    int idx = blockIdx.x * blockDim.x + threadIdx.x;
    if (idx >= N_BT) return;
    int b = idx / T_;
    int t = idx - b * T_;
    const int* m = metas + (size_t)idx * 5;
    int r = m[0], c = m[1], span = m[2], p = m[3];

    float hs = 0.5f * (float)span;
    cx[idx] = (float)c + hs;
    cy[idx] = (float)r + hs;
    sc[idx] = (p == 16) ? 1.0f : ((p == 8) ? 2.0f : 0.0f);

    if (p > 0) {
        int smax = span < 4 ? span : 4;
        for (int dr = 0; dr < smax; dr++) {
            for (int dc = 0; dc < smax; dc++) {
                int rr = r + dr, cc = c + dc;
                if (rr >= 0 && rr < G_ && cc >= 0 && cc < G_)
                    g_owner[b * (G_ * G_) + rr * G_ + cc] = t;
            }
        }
    }
}

// ---------------------------------------------------------------------------
// Kernel 2: patches — bilinear sample 8x8 per (b,t,cin)
// 16 blocks of 256 threads per token; local index = cin*64 + i*8 + j
// ---------------------------------------------------------------------------
__global__ void patches_kernel(const float* __restrict__ x_in,
                               const int* __restrict__ metas,
                               float* __restrict__ patches) {
    int blk   = blockIdx.x;
    int tok   = blk >> 4;                    // b*T + t
    int local = ((blk & 15) << 8) + threadIdx.x;   // 0..4095
    int cin = local >> 6;
    int i   = (local >> 3) & 7;
    int j   = local & 7;
    int b   = tok / T_;

    const int* m = metas + (size_t)tok * 5;
    int r = m[0], c = m[1], p = m[3];

    const float* img = x_in + ((size_t)(b * CIN_ + cin)) * (HF_ * HF_);
    float v = 0.0f;

    if (p == 16) {
        // pf=8 -> rel=i, w=0: pure crop
        v = __ldg(&img[(r * 4 + i) * HF_ + (c * 4 + j)]);
    } else if (p > 0) {
        int pf = p >> 1;                 // p // DOWN
        float pff = (float)(pf > 1 ? pf : 1);
        float scale = pff * 0.125f;      // pf / OUT
        float hi = pff - 1.0f;

        float rel_i = fminf(fmaxf(((float)i + 0.5f) * scale - 0.5f, 0.0f), hi);
        float rel_j = fminf(fmaxf(((float)j + 0.5f) * scale - 0.5f, 0.0f), hi);
        float i0f = floorf(rel_i); float wy = rel_i - i0f;
        float j0f = floorf(rel_j); float wx = rel_j - j0f;
        float i1f = fminf(i0f + 1.0f, hi);
        float j1f = fminf(j0f + 1.0f, hi);

        int y0 = r * 4 + (int)i0f;
        int y1 = r * 4 + (int)i1f;
        int x0 = c * 4 + (int)j0f;
        int x1 = c * 4 + (int)j1f;

        float a  = __ldg(&img[y0 * HF_ + x0]);
        float bv = __ldg(&img[y0 * HF_ + x1]);
        float cv = __ldg(&img[y1 * HF_ + x0]);
        float dv = __ldg(&img[y1 * HF_ + x1]);

        float top = a  * (1.0f - wx) + bv * wx;
        float bot = cv * (1.0f - wx) + dv * wx;
        v = top * (1.0f - wy) + bot * wy;
    }

    patches[(size_t)tok * 4096 + local] = v;
}

// ---------------------------------------------------------------------------
// Kernel 3: fmap gather — fmap[b,e,cell] = tokens[b, owner[b,cell], e]
// consecutive threads -> consecutive cells -> coalesced writes
// ---------------------------------------------------------------------------
__global__ void fmap_kernel(const float* __restrict__ tokens,
                            float* __restrict__ fmap) {
    int idx = blockIdx.x * blockDim.x + threadIdx.x;   // 0 .. B*E*1024
    if (idx >= N_FMAP) return;
    int cell = idx & (G_ * G_ - 1);
    int be   = idx >> 10;
    int e    = be % E_;
    int b    = be / E_;

    int own = g_owner[b * (G_ * G_) + cell];
    float v = 0.0f;
    if (own >= 0)
        v = __ldg(&tokens[((size_t)(b * T_ + own)) * E_ + e]);
    fmap[idx] = v;
}

// ---------------------------------------------------------------------------
extern "C" void kernel_launch(void* const* d_in, const int* in_sizes, int n_in,
                              void* d_out, int out_size) {
    const float* x_in   = (const float*)d_in[0];
    const float* tokens = (const float*)d_in[1];
    const int*   metas  = (const int*)d_in[2];

    float* out     = (float*)d_out;
    float* patches = out;
    float* cx      = out + (size_t)N_PATCHES;
    float* cy      = cx + N_BT;
    float* sc      = cy + N_BT;
    float* fmap    = sc + N_BT;

    init_owner_kernel<<<(B_ * G_ * G_ + 255) / 256, 256>>>();
    meta_kernel<<<(N_BT + 255) / 256, 256>>>(metas, cx, cy, sc);
    patches_kernel<<<N_BT * 16, 256>>>(x_in, metas, patches);
    fmap_kernel<<<(N_FMAP + 255) / 256, 256>>>(tokens, fmap);
}

// round 2
// speedup vs baseline: 1.9184x; 1.9184x over previous
#include <cuda_runtime.h>
#include <cstdint>

#define B_   8
#define T_   316
#define CIN_ 64
#define HF_  128
#define G_   32
#define E_   384

#define N_PATCHES (B_*T_*CIN_*64)
#define N_BT      (B_*T_)
#define N_FMAP    (B_*E_*G_*G_)

// scratch: owner map (which token owns each grid cell), per batch
__device__ int g_owner[B_ * G_ * G_];

// ---------------------------------------------------------------------------
// Kernel 0: init owner map to -1
// ---------------------------------------------------------------------------
__global__ void init_owner_kernel() {
    int idx = blockIdx.x * blockDim.x + threadIdx.x;
    if (idx < B_ * G_ * G_) g_owner[idx] = -1;
}

// ---------------------------------------------------------------------------
// Kernel 1: per-token meta -> cx, cy, scale_idx, owner scatter
// ---------------------------------------------------------------------------
__global__ void meta_kernel(const int* __restrict__ metas,
                            float* __restrict__ cx,
                            float* __restrict__ cy,
                            float* __restrict__ sc) {
    int idx = blockIdx.x * blockDim.x + threadIdx.x;
    if (idx >= N_BT) return;
    int b = idx / T_;
    int t = idx - b * T_;
    const int* m = metas + (size_t)idx * 5;
    int r = m[0], c = m[1], span = m[2], p = m[3];

    float hs = 0.5f * (float)span;
    cx[idx] = (float)c + hs;
    cy[idx] = (float)r + hs;
    sc[idx] = (p == 16) ? 1.0f : ((p == 8) ? 2.0f : 0.0f);

    if (p > 0) {
        int smax = span < 4 ? span : 4;
        for (int dr = 0; dr < smax; dr++) {
            for (int dc = 0; dc < smax; dc++) {
                int rr = r + dr, cc = c + dc;
                if (rr >= 0 && rr < G_ && cc >= 0 && cc < G_)
                    g_owner[b * (G_ * G_) + rr * G_ + cc] = t;
            }
        }
    }
}

// ---------------------------------------------------------------------------
// Kernel 2: patches — one thread computes one 8-wide output row.
// 512 threads per token (64 cin * 8 rows) = 2 blocks of 256.
// All loads/stores are 16B-vectorized and aligned.
// ---------------------------------------------------------------------------
__global__ void __launch_bounds__(256) patches_kernel(
        const float* __restrict__ x_in,
        const int* __restrict__ metas,
        float* __restrict__ patches) {
    int blk   = blockIdx.x;
    int tok   = blk >> 1;                        // b*T + t
    int local = ((blk & 1) << 8) + threadIdx.x;  // 0..511
    int cin = local >> 3;
    int i   = local & 7;
    int b   = tok / T_;

    const int* m = metas + (size_t)tok * 5;
    int r = m[0], c = m[1], p = m[3];

    const float4* img4 = (const float4*)(x_in + ((size_t)(b * CIN_ + cin)) * (HF_ * HF_));
    // img4 row stride = 32 float4s; col block at c (since c*4 floats = c float4s)
    float4 o0, o1;

    if (p == 16) {
        // pf=8 -> rel=i, w=0: pure 8x8 crop at (r*4, c*4)
        int row = r * 4 + i;
        o0 = img4[row * 32 + c];
        o1 = img4[row * 32 + c + 1];
    } else if (p > 0) {
        int pf = p >> 1; if (pf < 1) pf = 1;     // <= 4 here
        float pff   = (float)pf;
        float scale = pff * 0.125f;
        float hi    = pff - 1.0f;

        // vertical
        float rel_i = fminf(fmaxf(((float)i + 0.5f) * scale - 0.5f, 0.0f), hi);
        float i0f = floorf(rel_i);
        float wy  = rel_i - i0f;
        float i1f = fminf(i0f + 1.0f, hi);
        int y0 = r * 4 + (int)i0f;
        int y1 = r * 4 + (int)i1f;

        float4 t0 = img4[y0 * 32 + c];
        float4 t1 = img4[y1 * 32 + c];
        // blend rows once
        float rb[4];
        rb[0] = t0.x + (t1.x - t0.x) * wy;
        rb[1] = t0.y + (t1.y - t0.y) * wy;
        rb[2] = t0.z + (t1.z - t0.z) * wy;
        rb[3] = t0.w + (t1.w - t0.w) * wy;

        float out[8];
        #pragma unroll
        for (int j = 0; j < 8; j++) {
            float rel_j = fminf(fmaxf(((float)j + 0.5f) * scale - 0.5f, 0.0f), hi);
            float j0f = floorf(rel_j);
            float wx  = rel_j - j0f;
            int j0 = (int)j0f;
            int j1 = j0 + 1; if (j1 > (int)hi) j1 = (int)hi;
            out[j] = rb[j0] + (rb[j1] - rb[j0]) * wx;
        }
        o0 = make_float4(out[0], out[1], out[2], out[3]);
        o1 = make_float4(out[4], out[5], out[6], out[7]);
    } else {
        o0 = make_float4(0.f, 0.f, 0.f, 0.f);
        o1 = o0;
    }

    float4* dst = (float4*)(patches + (size_t)tok * 4096 + cin * 64 + i * 8);
    dst[0] = o0;
    dst[1] = o1;
}

// ---------------------------------------------------------------------------
// Kernel 3: fmap gather — thread = (b, e-group-of-4, cell).
// One aligned float4 read from tokens, 4 warp-coalesced writes.
// ---------------------------------------------------------------------------
__global__ void __launch_bounds__(256) fmap_kernel(
        const float* __restrict__ tokens,
        float* __restrict__ fmap) {
    int idx = blockIdx.x * blockDim.x + threadIdx.x;   // 0 .. N_FMAP/4
    if (idx >= N_FMAP / 4) return;
    int cell = idx & (G_ * G_ - 1);
    int be4  = idx >> 10;
    int e4   = be4 % (E_ / 4);      // 0..95
    int b    = be4 / (E_ / 4);
    int e    = e4 * 4;

    int own = g_owner[b * (G_ * G_) + cell];
    float4 v = make_float4(0.f, 0.f, 0.f, 0.f);
    if (own >= 0)
        v = *(const float4*)(tokens + ((size_t)(b * T_ + own)) * E_ + e);

    float* dst = fmap + ((size_t)(b * E_ + e)) * (G_ * G_) + cell;
    dst[0]            = v.x;
    dst[G_ * G_]      = v.y;
    dst[2 * G_ * G_]  = v.z;
    dst[3 * G_ * G_]  = v.w;
}

// ---------------------------------------------------------------------------
extern "C" void kernel_launch(void* const* d_in, const int* in_sizes, int n_in,
                              void* d_out, int out_size) {
    const float* x_in   = (const float*)d_in[0];
    const float* tokens = (const float*)d_in[1];
    const int*   metas  = (const int*)d_in[2];

    float* out     = (float*)d_out;
    float* patches = out;
    float* cx      = out + (size_t)N_PATCHES;
    float* cy      = cx + N_BT;
    float* sc      = cy + N_BT;
    float* fmap    = sc + N_BT;

    init_owner_kernel<<<(B_ * G_ * G_ + 255) / 256, 256>>>();
    meta_kernel<<<(N_BT + 255) / 256, 256>>>(metas, cx, cy, sc);
    patches_kernel<<<N_BT * 2, 256>>>(x_in, metas, patches);
    fmap_kernel<<<(N_FMAP / 4 + 255) / 256, 256>>>(tokens, fmap);
}

// round 3
// speedup vs baseline: 1.9507x; 1.0168x over previous
#include <cuda_runtime.h>
#include <cstdint>

#define B_   8
#define T_   316
#define CIN_ 64
#define HF_  128
#define G_   32
#define E_   384

#define N_PATCHES (B_*T_*CIN_*64)
#define N_BT      (B_*T_)
#define N_FMAP    (B_*E_*G_*G_)

// owner map: which token owns each grid cell (meta construction covers every
// cell exactly once, so no init / validity check is needed)
__device__ int g_owner[B_ * G_ * G_];

// ---------------------------------------------------------------------------
// Kernel 1: per-token meta -> cx, cy, scale_idx, owner scatter
// ---------------------------------------------------------------------------
__global__ void meta_kernel(const int* __restrict__ metas,
                            float* __restrict__ cx,
                            float* __restrict__ cy,
                            float* __restrict__ sc) {
    int idx = blockIdx.x * blockDim.x + threadIdx.x;
    if (idx >= N_BT) return;
    int b = idx / T_;
    int t = idx - b * T_;
    const int* m = metas + (size_t)idx * 5;
    int r = m[0], c = m[1], span = m[2], p = m[3];

    float hs = 0.5f * (float)span;
    cx[idx] = (float)c + hs;
    cy[idx] = (float)r + hs;
    sc[idx] = (p == 16) ? 1.0f : ((p == 8) ? 2.0f : 0.0f);

    if (p > 0) {
        int smax = span < 4 ? span : 4;
        for (int dr = 0; dr < smax; dr++) {
            for (int dc = 0; dc < smax; dc++) {
                int rr = r + dr, cc = c + dc;
                if (rr >= 0 && rr < G_ && cc >= 0 && cc < G_)
                    g_owner[b * (G_ * G_) + rr * G_ + cc] = t;
            }
        }
    }
}

// ---------------------------------------------------------------------------
// Kernel 2: patches — one thread computes one float4 of output.
// lane = (cin, i, half): lane pairs share an image row -> 16 distinct
// 128B lines per LDG.128 warp-instr (p==16) instead of 32; stores are
// fully coalesced 512B per warp-instr.
// ---------------------------------------------------------------------------
__global__ void __launch_bounds__(256) patches_kernel(
        const float* __restrict__ x_in,
        const int* __restrict__ metas,
        float* __restrict__ patches) {
    int blk   = blockIdx.x;
    int tok   = blk >> 2;                        // b*T + t
    int local = ((blk & 3) << 8) + threadIdx.x;  // 0..1023
    int half = local & 1;
    int i    = (local >> 1) & 7;
    int cin  = local >> 4;
    int b    = tok / T_;

    const int* m = metas + (size_t)tok * 5;
    int r = m[0], c = m[1], p = m[3];

    const float4* img4 = (const float4*)(x_in + ((size_t)(b * CIN_ + cin)) * (HF_ * HF_));
    float4 o;

    if (p == 16) {
        // pf=8 -> rel=i, w=0: pure 8x8 crop at (r*4, c*4)
        int row = r * 4 + i;
        o = img4[row * 32 + c + half];
    } else if (p > 0) {
        int pf = p >> 1; if (pf < 1) pf = 1;     // <= 4 here
        float pff   = (float)pf;
        float scale = pff * 0.125f;
        float hi    = pff - 1.0f;

        // vertical blend (footprint <= 4 cols -> one float4 per row)
        float rel_i = fminf(fmaxf(((float)i + 0.5f) * scale - 0.5f, 0.0f), hi);
        float i0f = floorf(rel_i);
        float wy  = rel_i - i0f;
        float i1f = fminf(i0f + 1.0f, hi);
        int y0 = r * 4 + (int)i0f;
        int y1 = r * 4 + (int)i1f;

        float4 t0 = img4[y0 * 32 + c];
        float4 t1 = img4[y1 * 32 + c];
        float rb[4];
        rb[0] = t0.x + (t1.x - t0.x) * wy;
        rb[1] = t0.y + (t1.y - t0.y) * wy;
        rb[2] = t0.z + (t1.z - t0.z) * wy;
        rb[3] = t0.w + (t1.w - t0.w) * wy;

        float out[4];
        #pragma unroll
        for (int jj = 0; jj < 4; jj++) {
            float j = (float)(half * 4 + jj);
            float rel_j = fminf(fmaxf((j + 0.5f) * scale - 0.5f, 0.0f), hi);
            float j0f = floorf(rel_j);
            float wx  = rel_j - j0f;
            int j0 = (int)j0f;
            int j1 = j0 + 1; if (j1 > (int)hi) j1 = (int)hi;
            out[jj] = rb[j0] + (rb[j1] - rb[j0]) * wx;
        }
        o = make_float4(out[0], out[1], out[2], out[3]);
    } else {
        o = make_float4(0.f, 0.f, 0.f, 0.f);
    }

    ((float4*)patches)[(size_t)tok * 1024 + local] = o;
}

// ---------------------------------------------------------------------------
// Kernel 3: fmap gather — thread = (b, e-chunk of 8 float4 groups, cell).
// 1 owner load amortized over 8 independent contiguous float4 token loads
// (128B streamed from one token row) + 32 warp-coalesced scalar stores.
// ---------------------------------------------------------------------------
#define ECHUNKS 12   // 96 e4-groups / 8 per thread

__global__ void __launch_bounds__(256) fmap_kernel(
        const float* __restrict__ tokens,
        float* __restrict__ fmap) {
    int idx  = blockIdx.x * blockDim.x + threadIdx.x;  // 0 .. B*12*1024
    int cell = idx & (G_ * G_ - 1);
    int rest = idx >> 10;
    int chunk = rest % ECHUNKS;
    int b     = rest / ECHUNKS;

    int own = g_owner[b * (G_ * G_) + cell];
    const float4* src = (const float4*)(tokens + ((size_t)(b * T_ + own)) * E_) + chunk * 8;

    float4 v[8];
    #pragma unroll
    for (int k = 0; k < 8; k++) v[k] = src[k];

    float* dst = fmap + ((size_t)(b * E_ + chunk * 32)) * (G_ * G_) + cell;
    #pragma unroll
    for (int k = 0; k < 8; k++) {
        dst[(k * 4 + 0) * (G_ * G_)] = v[k].x;
        dst[(k * 4 + 1) * (G_ * G_)] = v[k].y;
        dst[(k * 4 + 2) * (G_ * G_)] = v[k].z;
        dst[(k * 4 + 3) * (G_ * G_)] = v[k].w;
    }
}

// ---------------------------------------------------------------------------
extern "C" void kernel_launch(void* const* d_in, const int* in_sizes, int n_in,
                              void* d_out, int out_size) {
    const float* x_in   = (const float*)d_in[0];
    const float* tokens = (const float*)d_in[1];
    const int*   metas  = (const int*)d_in[2];

    float* out     = (float*)d_out;
    float* patches = out;
    float* cx      = out + (size_t)N_PATCHES;
    float* cy      = cx + N_BT;
    float* sc      = cy + N_BT;
    float* fmap    = sc + N_BT;

    meta_kernel<<<(N_BT + 255) / 256, 256>>>(metas, cx, cy, sc);
    patches_kernel<<<N_BT * 4, 256>>>(x_in, metas, patches);
    fmap_kernel<<<(B_ * ECHUNKS * G_ * G_) / 256, 256>>>(tokens, fmap);
}

// round 4
// speedup vs baseline: 1.9865x; 1.0184x over previous
#include <cuda_runtime.h>
#include <cstdint>

#define B_   8
#define T_   316
#define CIN_ 64
#define HF_  128
#define G_   32
#define E_   384

#define N_PATCHES (B_*T_*CIN_*64)
#define N_BT      (B_*T_)
#define N_FMAP    (B_*E_*G_*G_)

// owner map: which token owns each grid cell (meta construction covers every
// cell exactly once, so no init / validity check is needed)
__device__ int g_owner[B_ * G_ * G_];

// ---------------------------------------------------------------------------
// Kernel A: patches (one thread = one float4 of output) with the per-token
// meta work (cx/cy/scale + owner scatter) fused into thread 0 of each
// token's first block. No separate meta launch.
// ---------------------------------------------------------------------------
__global__ void __launch_bounds__(256) patches_meta_kernel(
        const float* __restrict__ x_in,
        const int* __restrict__ metas,
        float* __restrict__ patches,
        float* __restrict__ cx,
        float* __restrict__ cy,
        float* __restrict__ sc) {
    int blk   = blockIdx.x;
    int tok   = blk >> 2;                        // b*T + t
    int local = ((blk & 3) << 8) + threadIdx.x;  // 0..1023
    int half = local & 1;
    int i    = (local >> 1) & 7;
    int cin  = local >> 4;
    int b    = tok / T_;

    const int* m = metas + (size_t)tok * 5;
    int r = m[0], c = m[1], p = m[3];

    // --- fused meta (one thread per token) ---
    if (local == 0) {
        int span = m[2];
        int t = tok - b * T_;
        float hs = 0.5f * (float)span;
        cx[tok] = (float)c + hs;
        cy[tok] = (float)r + hs;
        sc[tok] = (p == 16) ? 1.0f : ((p == 8) ? 2.0f : 0.0f);
        if (p > 0) {
            int smax = span < 4 ? span : 4;
            for (int dr = 0; dr < smax; dr++)
                for (int dc = 0; dc < smax; dc++) {
                    int rr = r + dr, cc2 = c + dc;
                    if (rr >= 0 && rr < G_ && cc2 >= 0 && cc2 < G_)
                        g_owner[b * (G_ * G_) + rr * G_ + cc2] = t;
                }
        }
    }

    const float4* img4 = (const float4*)(x_in + ((size_t)(b * CIN_ + cin)) * (HF_ * HF_));
    float4 o;

    if (p == 16) {
        // pf=8 -> rel=i, w=0: pure 8x8 crop at (r*4, c*4)
        int row = r * 4 + i;
        o = img4[row * 32 + c + half];
    } else if (p > 0) {
        int pf = p >> 1; if (pf < 1) pf = 1;     // <= 4 here
        float pff   = (float)pf;
        float scale = pff * 0.125f;
        float hi    = pff - 1.0f;

        float rel_i = fminf(fmaxf(((float)i + 0.5f) * scale - 0.5f, 0.0f), hi);
        float i0f = floorf(rel_i);
        float wy  = rel_i - i0f;
        float i1f = fminf(i0f + 1.0f, hi);
        int y0 = r * 4 + (int)i0f;
        int y1 = r * 4 + (int)i1f;

        float4 t0 = img4[y0 * 32 + c];
        float4 t1 = img4[y1 * 32 + c];
        float rb[4];
        rb[0] = t0.x + (t1.x - t0.x) * wy;
        rb[1] = t0.y + (t1.y - t0.y) * wy;
        rb[2] = t0.z + (t1.z - t0.z) * wy;
        rb[3] = t0.w + (t1.w - t0.w) * wy;

        float out[4];
        #pragma unroll
        for (int jj = 0; jj < 4; jj++) {
            float j = (float)(half * 4 + jj);
            float rel_j = fminf(fmaxf((j + 0.5f) * scale - 0.5f, 0.0f), hi);
            float j0f = floorf(rel_j);
            float wx  = rel_j - j0f;
            int j0 = (int)j0f;
            int j1 = j0 + 1; if (j1 > (int)hi) j1 = (int)hi;
            out[jj] = rb[j0] + (rb[j1] - rb[j0]) * wx;
        }
        o = make_float4(out[0], out[1], out[2], out[3]);
    } else {
        o = make_float4(0.f, 0.f, 0.f, 0.f);
    }

    ((float4*)patches)[(size_t)tok * 1024 + local] = o;
}

// ---------------------------------------------------------------------------
// Kernel B: fmap via shared-memory transpose.
// Block = one grid row (32 cells) of one batch.
// Phase 1: each warp owns 4 cells; loads each owner's 384-float token row
//          fully coalesced, stores into smem with (e+cell)%384 rotation
//          (conflict-free: 384 % 32 == 0, rotation = bank rotation).
// Phase 2: lane = cell, warp covers 48 e-values; conflict-free LDS +
//          fully coalesced 128B stores.
// ---------------------------------------------------------------------------
__global__ void __launch_bounds__(256) fmap_kernel(
        const float* __restrict__ tokens,
        float* __restrict__ fmap) {
    __shared__ float sm[32 * E_];   // 48 KB

    int bk    = blockIdx.x;          // 0 .. B*32-1
    int b     = bk >> 5;
    int cell0 = (bk & 31) << 5;      // one full grid row
    int tid   = threadIdx.x;
    int lane  = tid & 31;
    int w     = tid >> 5;

    // phase 1: coalesced token-row loads -> rotated smem
    #pragma unroll
    for (int cc = 0; cc < 4; cc++) {
        int cell = w * 4 + cc;
        int own  = g_owner[b * (G_ * G_) + cell0 + cell];
        const float* src = tokens + ((size_t)(b * T_ + own)) * E_;
        #pragma unroll
        for (int it = 0; it < 12; it++) {
            int e  = it * 32 + lane;
            int es = e + cell; if (es >= E_) es -= E_;
            sm[cell * E_ + es] = __ldg(&src[e]);
        }
    }
    __syncthreads();

    // phase 2: conflict-free LDS -> coalesced stores
    float* dstb = fmap + (size_t)b * E_ * (G_ * G_) + cell0 + lane;
    #pragma unroll
    for (int k = 0; k < 48; k++) {
        int e  = w * 48 + k;
        int es = e + lane; if (es >= E_) es -= E_;
        dstb[(size_t)e * (G_ * G_)] = sm[lane * E_ + es];
    }
}

// ---------------------------------------------------------------------------
extern "C" void kernel_launch(void* const* d_in, const int* in_sizes, int n_in,
                              void* d_out, int out_size) {
    const float* x_in   = (const float*)d_in[0];
    const float* tokens = (const float*)d_in[1];
    const int*   metas  = (const int*)d_in[2];

    float* out     = (float*)d_out;
    float* patches = out;
    float* cx      = out + (size_t)N_PATCHES;
    float* cy      = cx + N_BT;
    float* sc      = cy + N_BT;
    float* fmap    = sc + N_BT;

    patches_meta_kernel<<<N_BT * 4, 256>>>(x_in, metas, patches, cx, cy, sc);
    fmap_kernel<<<B_ * G_, 256>>>(tokens, fmap);
}

// round 5
// speedup vs baseline: 2.2573x; 1.1363x over previous
#include <cuda_runtime.h>
#include <cstdint>

#define B_   8
#define T_   316
#define CIN_ 64
#define HF_  128
#define G_   32
#define E_   384

#define N_PATCHES (B_*T_*CIN_*64)
#define N_BT      (B_*T_)

// fmap blocks: (batch, grid-row, e-quarter)  -> 8*32*4 = 1024
#define FMAP_BLOCKS   (B_ * G_ * 4)
#define PATCH_BLOCKS  (N_BT * 4)
#define EQ_           96        // e-values per fmap block (384/4)
#define SMS_          97        // smem row stride (+1 pad: conflict-free both phases)

// ---------------------------------------------------------------------------
// Single fused kernel.
//   blocks [0, FMAP_BLOCKS):            fmap transpose-gather
//   blocks [FMAP_BLOCKS, +PATCH_BLOCKS): patches + per-token meta
// fmap blocks recompute cell owners from metas directly (meta construction
// tiles the 32x32 grid exactly once), so there is no inter-block dependency.
// ---------------------------------------------------------------------------
__global__ void __launch_bounds__(256) fused_kernel(
        const float* __restrict__ x_in,
        const float* __restrict__ tokens,
        const int*   __restrict__ metas,
        float* __restrict__ patches,
        float* __restrict__ cx,
        float* __restrict__ cy,
        float* __restrict__ sc,
        float* __restrict__ fmap) {

    __shared__ float sm[32 * SMS_];   // ~12.4 KB
    __shared__ int   s_own[32];

    int tid = threadIdx.x;

    if (blockIdx.x < FMAP_BLOCKS) {
        // ------------------------- fmap path -------------------------
        int fb  = blockIdx.x;
        int q   = fb & 3;              // e-quarter
        int row = (fb >> 2) & 31;      // grid row
        int b   = fb >> 7;             // batch
        int lane = tid & 31;
        int w    = tid >> 5;

        // owners for this grid row, from metas (coverage is exact)
        for (int t = tid; t < T_; t += 256) {
            const int* m = metas + (size_t)(b * T_ + t) * 5;
            int r = m[0], c = m[1], span = m[2], p = m[3];
            int di = row - r;
            if (p > 0 && di >= 0 && di < span) {
                for (int dc = 0; dc < span; dc++) {
                    int col = c + dc;
                    if (col >= 0 && col < G_) s_own[col] = t;
                }
            }
        }
        __syncthreads();

        // phase 1: coalesced token loads -> smem (fixed cell row: no conflicts)
        int e0 = q * EQ_;
        #pragma unroll
        for (int cc = 0; cc < 4; cc++) {
            int cell = w * 4 + cc;
            const float* src = tokens +
                ((size_t)(b * T_ + s_own[cell])) * E_ + e0;
            #pragma unroll
            for (int it = 0; it < 3; it++) {
                int e = it * 32 + lane;
                sm[cell * SMS_ + e] = __ldg(&src[e]);
            }
        }
        __syncthreads();

        // phase 2: lane = cell -> fully coalesced 128B stores
        // warp w covers e_local in [w*12, w*12+12)
        float* dstb = fmap + ((size_t)(b * E_ + e0) + w * 12) * (G_ * G_)
                           + row * 32 + lane;
        #pragma unroll
        for (int k = 0; k < 12; k++) {
            dstb[(size_t)k * (G_ * G_)] = sm[lane * SMS_ + w * 12 + k];
        }
        return;
    }

    // --------------------------- patches path ---------------------------
    int blk   = blockIdx.x - FMAP_BLOCKS;
    int tok   = blk >> 2;                        // b*T + t
    int local = ((blk & 3) << 8) + tid;          // 0..1023
    int half = local & 1;
    int i    = (local >> 1) & 7;
    int cin  = local >> 4;
    int b    = tok / T_;

    const int* m = metas + (size_t)tok * 5;
    int r = m[0], c = m[1], p = m[3];

    // fused meta (one thread per token)
    if (local == 0) {
        int span = m[2];
        float hs = 0.5f * (float)span;
        cx[tok] = (float)c + hs;
        cy[tok] = (float)r + hs;
        sc[tok] = (p == 16) ? 1.0f : ((p == 8) ? 2.0f : 0.0f);
    }

    const float4* img4 = (const float4*)(x_in + ((size_t)(b * CIN_ + cin)) * (HF_ * HF_));
    float4 o;

    if (p == 16) {
        // pf=8 -> rel=i, w=0: pure 8x8 crop at (r*4, c*4)
        int rowp = r * 4 + i;
        o = img4[rowp * 32 + c + half];
    } else if (p > 0) {
        int pf = p >> 1; if (pf < 1) pf = 1;     // <= 4 here
        float pff   = (float)pf;
        float scale = pff * 0.125f;
        float hi    = pff - 1.0f;

        float rel_i = fminf(fmaxf(((float)i + 0.5f) * scale - 0.5f, 0.0f), hi);
        float i0f = floorf(rel_i);
        float wy  = rel_i - i0f;
        float i1f = fminf(i0f + 1.0f, hi);
        int y0 = r * 4 + (int)i0f;
        int y1 = r * 4 + (int)i1f;

        float4 t0 = img4[y0 * 32 + c];
        float4 t1 = img4[y1 * 32 + c];
        float rb[4];
        rb[0] = t0.x + (t1.x - t0.x) * wy;
        rb[1] = t0.y + (t1.y - t0.y) * wy;
        rb[2] = t0.z + (t1.z - t0.z) * wy;
        rb[3] = t0.w + (t1.w - t0.w) * wy;

        float out[4];
        #pragma unroll
        for (int jj = 0; jj < 4; jj++) {
            float j = (float)(half * 4 + jj);
            float rel_j = fminf(fmaxf((j + 0.5f) * scale - 0.5f, 0.0f), hi);
            float j0f = floorf(rel_j);
            float wx  = rel_j - j0f;
            int j0 = (int)j0f;
            int j1 = j0 + 1; if (j1 > (int)hi) j1 = (int)hi;
            out[jj] = rb[j0] + (rb[j1] - rb[j0]) * wx;
        }
        o = make_float4(out[0], out[1], out[2], out[3]);
    } else {
        o = make_float4(0.f, 0.f, 0.f, 0.f);
    }

    ((float4*)patches)[(size_t)tok * 1024 + local] = o;
}

// ---------------------------------------------------------------------------
extern "C" void kernel_launch(void* const* d_in, const int* in_sizes, int n_in,
                              void* d_out, int out_size) {
    const float* x_in   = (const float*)d_in[0];
    const float* tokens = (const float*)d_in[1];
    const int*   metas  = (const int*)d_in[2];

    float* out     = (float*)d_out;
    float* patches = out;
    float* cx      = out + (size_t)N_PATCHES;
    float* cy      = cx + N_BT;
    float* sc      = cy + N_BT;
    float* fmap    = sc + N_BT;

    fused_kernel<<<FMAP_BLOCKS + PATCH_BLOCKS, 256>>>(
        x_in, tokens, metas, patches, cx, cy, sc, fmap);
}

// round 6
// speedup vs baseline: 2.5885x; 1.1467x over previous
#include <cuda_runtime.h>
#include <cstdint>

#define B_   8
#define T_   316
#define CIN_ 64
#define HF_  128
#define G_   32
#define E_   384

#define N_PATCHES (B_*T_*CIN_*64)
#define N_BT      (B_*T_)

// fmap blocks: (batch, grid-row, e-quarter) -> 8*32*4 = 1024
#define FMAP_BLOCKS  (B_ * G_ * 4)
#define EQ_          96        // e-values per fmap block (384/4)
#define SMS_         97        // smem row stride (pad: conflict-free)

// ---------------------------------------------------------------------------
// Single fused kernel.
//   blocks [0, N_BT):          patches + per-token meta (1 block = 1 token,
//                              each thread produces 4 float4s, k-chunked so
//                              weights/indices amortize over 4 cins and
//                              stores stay perfectly coalesced)
//   blocks [N_BT, +FMAP_BLOCKS): fmap transpose-gather (owners recomputed
//                              from metas; grid coverage is exact)
// ---------------------------------------------------------------------------
__global__ void __launch_bounds__(256) fused_kernel(
        const float* __restrict__ x_in,
        const float* __restrict__ tokens,
        const int*   __restrict__ metas,
        float* __restrict__ patches,
        float* __restrict__ cx,
        float* __restrict__ cy,
        float* __restrict__ sc,
        float* __restrict__ fmap) {

    int tid = threadIdx.x;

    if (blockIdx.x < N_BT) {
        // --------------------------- patches ---------------------------
        int tok = blockIdx.x;
        int b   = tok / T_;

        const int* m = metas + (size_t)tok * 5;
        int r = m[0], c = m[1], p = m[3];

        if (tid == 0) {
            int span = m[2];
            float hs = 0.5f * (float)span;
            cx[tok] = (float)c + hs;
            cy[tok] = (float)r + hs;
            sc[tok] = (p == 16) ? 1.0f : ((p == 8) ? 2.0f : 0.0f);
        }

        // decode (invariant in k): half = bit0, i = bits1-3, cin0 = bits4-7
        int half = tid & 1;
        int i    = (tid >> 1) & 7;
        int cin0 = tid >> 4;           // 0..15 ; cin = cin0 + 16k

        const float* img_base = x_in + ((size_t)b * CIN_ + cin0) * (HF_ * HF_);
        float4* dst = ((float4*)patches) + (size_t)tok * 1024 + tid;

        if (p == 16) {
            // pure 8x8 crop at (r*4, c*4)
            int off = (r * 4 + i) * 32 + c + half;   // float4 units
            float4 v[4];
            #pragma unroll
            for (int k = 0; k < 4; k++)
                v[k] = __ldg((const float4*)img_base + (size_t)k * 16 * (HF_ * HF_ / 4) + off);
            #pragma unroll
            for (int k = 0; k < 4; k++)
                __stcs(dst + k * 256, v[k]);
        } else if (p > 0) {
            int pf = p >> 1; if (pf < 1) pf = 1;     // <= 4 here
            float pff   = (float)pf;
            float scale = pff * 0.125f;
            float hi    = pff - 1.0f;

            // vertical weights (once)
            float rel_i = fminf(fmaxf(((float)i + 0.5f) * scale - 0.5f, 0.0f), hi);
            float i0f = floorf(rel_i);
            float wy  = rel_i - i0f;
            float i1f = fminf(i0f + 1.0f, hi);
            int y0off = (r * 4 + (int)i0f) * 32 + c;
            int y1off = (r * 4 + (int)i1f) * 32 + c;

            // horizontal weights (once)
            int   j0[4], j1[4];
            float wx[4];
            #pragma unroll
            for (int jj = 0; jj < 4; jj++) {
                float j = (float)(half * 4 + jj);
                float rel_j = fminf(fmaxf((j + 0.5f) * scale - 0.5f, 0.0f), hi);
                float j0f = floorf(rel_j);
                wx[jj] = rel_j - j0f;
                j0[jj] = (int)j0f;
                int t1 = j0[jj] + 1; if (t1 > (int)hi) t1 = (int)hi;
                j1[jj] = t1;
            }

            float4 t0[4], t1[4];
            #pragma unroll
            for (int k = 0; k < 4; k++) {
                const float4* img4 = (const float4*)img_base + (size_t)k * 16 * (HF_ * HF_ / 4);
                t0[k] = __ldg(img4 + y0off);
                t1[k] = __ldg(img4 + y1off);
            }
            #pragma unroll
            for (int k = 0; k < 4; k++) {
                float rb[4];
                rb[0] = t0[k].x + (t1[k].x - t0[k].x) * wy;
                rb[1] = t0[k].y + (t1[k].y - t0[k].y) * wy;
                rb[2] = t0[k].z + (t1[k].z - t0[k].z) * wy;
                rb[3] = t0[k].w + (t1[k].w - t0[k].w) * wy;
                float4 o;
                o.x = rb[j0[0]] + (rb[j1[0]] - rb[j0[0]]) * wx[0];
                o.y = rb[j0[1]] + (rb[j1[1]] - rb[j0[1]]) * wx[1];
                o.z = rb[j0[2]] + (rb[j1[2]] - rb[j0[2]]) * wx[2];
                o.w = rb[j0[3]] + (rb[j1[3]] - rb[j0[3]]) * wx[3];
                __stcs(dst + k * 256, o);
            }
        } else {
            float4 z = make_float4(0.f, 0.f, 0.f, 0.f);
            #pragma unroll
            for (int k = 0; k < 4; k++) __stcs(dst + k * 256, z);
        }
        return;
    }

    // ----------------------------- fmap -----------------------------
    __shared__ float sm[32 * SMS_];   // ~12.4 KB
    __shared__ int   s_own[32];

    int fb  = blockIdx.x - N_BT;
    int q   = fb & 3;              // e-quarter
    int row = (fb >> 2) & 31;      // grid row
    int b   = fb >> 7;             // batch
    int lane = tid & 31;
    int w    = tid >> 5;

    // owners for this grid row, from metas (coverage is exact, no races)
    for (int t = tid; t < T_; t += 256) {
        const int* m = metas + (size_t)(b * T_ + t) * 5;
        int r = m[0], c = m[1], span = m[2], p = m[3];
        int di = row - r;
        if (p > 0 && di >= 0 && di < span) {
            for (int dc = 0; dc < span; dc++) {
                int col = c + dc;
                if (col >= 0 && col < G_) s_own[col] = t;
            }
        }
    }
    __syncthreads();

    // phase 1: coalesced token loads -> smem
    int e0 = q * EQ_;
    #pragma unroll
    for (int cc = 0; cc < 4; cc++) {
        int cell = w * 4 + cc;
        const float* src = tokens + ((size_t)(b * T_ + s_own[cell])) * E_ + e0;
        #pragma unroll
        for (int it = 0; it < 3; it++) {
            int e = it * 32 + lane;
            sm[cell * SMS_ + e] = __ldg(&src[e]);
        }
    }
    __syncthreads();

    // phase 2: lane = cell -> fully coalesced 128B stores
    float* dstb = fmap + ((size_t)(b * E_ + e0) + w * 12) * (G_ * G_)
                       + row * 32 + lane;
    #pragma unroll
    for (int k = 0; k < 12; k++)
        __stcs(&dstb[(size_t)k * (G_ * G_)], sm[lane * SMS_ + w * 12 + k]);
}

// ---------------------------------------------------------------------------
extern "C" void kernel_launch(void* const* d_in, const int* in_sizes, int n_in,
                              void* d_out, int out_size) {
    const float* x_in   = (const float*)d_in[0];
    const float* tokens = (const float*)d_in[1];
    const int*   metas  = (const int*)d_in[2];

    float* out     = (float*)d_out;
    float* patches = out;
    float* cx      = out + (size_t)N_PATCHES;
    float* cy      = cx + N_BT;
    float* sc      = cy + N_BT;
    float* fmap    = sc + N_BT;

    fused_kernel<<<N_BT + FMAP_BLOCKS, 256>>>(
        x_in, tokens, metas, patches, cx, cy, sc, fmap);
}